// round 12
// baseline (speedup 1.0000x reference)
#include <cuda_runtime.h>
#include <math.h>

#define NPTS  2048
#define PAIRS 64
#define IVALS 16

// ---- scratch (no allocations allowed) --------------------------------------
__device__ float4   g_y[PAIRS * NPTS];      // transformed source: xyz + |y|^2
__device__ float4   g_x[IVALS * NPTS];      // target prescaled: -2x,-2y,-2z, |x|^2
__device__ unsigned g_colmin[PAIRS * NPTS]; // per-(pair,m) min d2, uint bits
__device__ float    g_rowpart[PAIRS * 16];  // per-(pair,nsplit) row-min sums
__device__ unsigned g_count[PAIRS];         // per-pair block arrival counter

// ---------------------------------------------------------------------------
// Kernel 1: transform source, prescale target, init colmin + counters.
// (measured-best shape: 512 blocks x 256 thr, 1 pt/thread)
// ---------------------------------------------------------------------------
__global__ void __launch_bounds__(256) prep_kernel(const float* __restrict__ src,
                            const float* __restrict__ tgt,
                            const float* __restrict__ rot,
                            const float* __restrict__ trn,
                            const float* __restrict__ scl)
{
    __shared__ float M[13];
    const int pair  = blockIdx.x >> 3;
    const int pbase = (blockIdx.x & 7) * 256;

    if (threadIdx.x == 0) {
        float ax = rot[pair * 3 + 0], ay = rot[pair * 3 + 1], az = rot[pair * 3 + 2];
        float sx, cx, sy, cy, sz, cz;
        sincosf(ax, &sx, &cx);
        sincosf(ay, &sy, &cy);
        sincosf(az, &sz, &cz);
        M[0] = cy * cz;                M[1] = -cy * sz;               M[2] = sy;
        M[3] = cx * sz + sx * sy * cz; M[4] = cx * cz - sx * sy * sz; M[5] = -sx * cy;
        M[6] = sx * sz - cx * sy * cz; M[7] = sx * cz + cx * sy * sz; M[8] = cx * cy;
        M[9]  = trn[pair * 3 + 0];
        M[10] = trn[pair * 3 + 1];
        M[11] = trn[pair * 3 + 2];
        M[12] = scl[pair];
    }
    if (threadIdx.x == 32 && (blockIdx.x & 7) == 0) g_count[pair] = 0;
    __syncthreads();

    const int idx = pair * NPTS + pbase + threadIdx.x;
    const float px = src[idx * 3 + 0];
    const float py = src[idx * 3 + 1];
    const float pz = src[idx * 3 + 2];
    const float s = M[12];
    const float qx = s * fmaf(M[0], px, fmaf(M[1], py, fmaf(M[2], pz, M[9])));
    const float qy = s * fmaf(M[3], px, fmaf(M[4], py, fmaf(M[5], pz, M[10])));
    const float qz = s * fmaf(M[6], px, fmaf(M[7], py, fmaf(M[8], pz, M[11])));

    g_y[idx] = make_float4(qx, qy, qz, qx * qx + qy * qy + qz * qz);
    g_colmin[idx] = 0x7F800000u;   // +inf bits

    if (pair < IVALS) {
        const float bx = tgt[idx * 3 + 0];
        const float by = tgt[idx * 3 + 1];
        const float bz = tgt[idx * 3 + 2];
        g_x[idx] = make_float4(-2.0f * bx, -2.0f * by, -2.0f * bz,
                               bx * bx + by * by + bz * bz);
    }
}

// ---------------------------------------------------------------------------
// Kernel 2: bidirectional chamfer (R9 pipelined loop, UNCHANGED) + fused
// per-pair finalize (last block per pair via threadfence + atomic counter).
// Block (nsplit, pair): 128 target rows x 2048 source cols, 16 chunks of 128.
// One barrier per chunk; double-buffered s_y and s_red; col-min reduce +
// atomicMin after the barrier overlaps the next chunk's compute.
//   c  = fma(xx,yx, fma(xy,yy, fma(xz,yz, yw)))   // |y|^2 - 2 x.y
//   rowmin over c (x2 deferred), colmin over c + x2.
// ---------------------------------------------------------------------------
__global__ void __launch_bounds__(256, 3) chamfer_kernel(float* __restrict__ out)
{
    const int pair   = blockIdx.y;
    const int nsplit = blockIdx.x;
    const int t  = threadIdx.x;
    const int tn = t >> 4;
    const int tm = t & 15;

    __shared__ float4 s_y[2][128];
    __shared__ float  s_red[2][16][129];
    __shared__ float  s_sum[8];
    __shared__ int    s_last;

    const float4* gx = g_x + (pair & 15) * NPTS + nsplit * 128;
    const float4* gy = g_y + pair * NPTS;
    unsigned* cmin = g_colmin + pair * NPTS;

    float4 xf[8];
#pragma unroll
    for (int i = 0; i < 8; i++) xf[i] = gx[tn * 8 + i];

    float rm[8];
#pragma unroll
    for (int i = 0; i < 8; i++) rm[i] = 3.4e38f;

    // prologue: stage chunk 0
    if (t < 128) s_y[0][t] = gy[t];
    __syncthreads();

    for (int c = 0; c < 16; c++) {
        // issue next chunk's load early (hidden behind compute)
        float4 nxt;
        if (c < 15 && t < 128) nxt = gy[(c + 1) * 128 + t];

        const float4* yb = &s_y[c & 1][0];

        float cm[8];
#pragma unroll
        for (int j = 0; j < 8; j++) cm[j] = 3.4e38f;

#pragma unroll
        for (int jj = 0; jj < 8; jj++) {
            const float4 y = yb[tm + 16 * jj];
#pragma unroll
            for (int i = 0; i < 8; i++) {
                float cc = fmaf(xf[i].x, y.x,
                           fmaf(xf[i].y, y.y,
                           fmaf(xf[i].z, y.z, y.w)));
                rm[i]  = fminf(rm[i], cc);
                cm[jj] = fminf(cm[jj], cc + xf[i].w);
            }
        }

        // stage col-min partials + next y buffer, then the chunk's ONE barrier
#pragma unroll
        for (int jj = 0; jj < 8; jj++) s_red[c & 1][tn][tm + 16 * jj] = cm[jj];
        if (c < 15 && t < 128) s_y[(c + 1) & 1][t] = nxt;
        __syncthreads();

        // reduce + atomic AFTER the barrier: overlaps next chunk's compute
        if (t < 128) {
            float v = s_red[c & 1][0][t];
#pragma unroll
            for (int k = 1; k < 16; k++) v = fminf(v, s_red[c & 1][k][t]);
            v = fmaxf(v, 0.0f);          // d2 >= 0: keep uint ordering monotone
            atomicMin(&cmin[c * 128 + t], __float_as_uint(v));
        }
    }

    // finalize row mins: add deferred x2, reduce over tm, sum the 128 rows
#pragma unroll
    for (int i = 0; i < 8; i++) s_red[0][tm][tn * 8 + i] = rm[i] + xf[i].w;
    __syncthreads();

    float total = 0.0f;
    if (t < 128) {
        float v = s_red[0][0][t];
#pragma unroll
        for (int k = 1; k < 16; k++) v = fminf(v, s_red[0][k][t]);
        total = v;
    }
#pragma unroll
    for (int off = 16; off > 0; off >>= 1)
        total += __shfl_down_sync(0xffffffffu, total, off);
    if ((t & 31) == 0) s_sum[t >> 5] = total;
    __syncthreads();
    if (t == 0) {
        g_rowpart[pair * 16 + nsplit] =
            s_sum[0] + s_sum[1] + s_sum[2] + s_sum[3] +
            s_sum[4] + s_sum[5] + s_sum[6] + s_sum[7];
    }

    // -------- fused finalize: last block of this pair computes the output ---
    __threadfence();                     // make rowpart STG + colmin REDG visible
    __syncthreads();                     // all threads' fences precede the add
    if (t == 0) s_last = (atomicAdd(&g_count[pair], 1u) == 15u);
    __syncthreads();
    if (!s_last) return;

    __threadfence();                     // acquire side of the counter protocol
    float local = 0.0f;
#pragma unroll
    for (int k = 0; k < 8; k++)
        local += __uint_as_float(__ldcg(&cmin[t + 256 * k]));
    if (t < 16) local += __ldcg(&g_rowpart[pair * 16 + t]);

    float* sbuf = &s_red[0][0][0];       // reuse shared
    sbuf[t] = local;
    __syncthreads();
#pragma unroll
    for (int s = 128; s > 0; s >>= 1) {
        if (t < s) sbuf[t] += sbuf[t + s];
        __syncthreads();
    }
    if (t == 0) out[pair] = sbuf[0] * (1.0f / 2048.0f);
}

// ---------------------------------------------------------------------------
extern "C" void kernel_launch(void* const* d_in, const int* in_sizes, int n_in,
                              void* d_out, int out_size)
{
    const float* src = (const float*)d_in[0];   // [4,16,2048,3]
    const float* tgt = (const float*)d_in[1];   // [16,2048,3]
    const float* rot = (const float*)d_in[2];   // [4,16,3]
    const float* trn = (const float*)d_in[3];   // [4,16,3]
    const float* scl = (const float*)d_in[4];   // [4,16]
    (void)in_sizes; (void)n_in; (void)out_size;

    prep_kernel<<<512, 256>>>(src, tgt, rot, trn, scl);
    chamfer_kernel<<<dim3(16, PAIRS), 256>>>((float*)d_out);
}

// round 13
// speedup vs baseline: 1.0228x; 1.0228x over previous
#include <cuda_runtime.h>
#include <math.h>

#define NPTS  2048
#define PAIRS 64
#define IVALS 16

typedef unsigned long long ull;

// ---- scratch (no allocations allowed) --------------------------------------
__device__ float4   g_y[PAIRS * NPTS];      // transformed source: xyz + |y|^2
__device__ float4   g_x[IVALS * NPTS];      // target prescaled: -2x,-2y,-2z, |x|^2
__device__ unsigned g_colmin[PAIRS * NPTS]; // per-(pair,m) min d2, uint bits
__device__ float    g_rowpart[PAIRS * 16];  // per-(pair,nsplit) row-min sums

// ---- packed f32x2 helpers ---------------------------------------------------
__device__ __forceinline__ ull fma2(ull a, ull b, ull c)
{
    ull d;
    asm("fma.rn.f32x2 %0, %1, %2, %3;" : "=l"(d) : "l"(a), "l"(b), "l"(c));
    return d;
}
__device__ __forceinline__ ull add2(ull a, ull b)
{
    ull d;
    asm("add.rn.f32x2 %0, %1, %2;" : "=l"(d) : "l"(a), "l"(b));
    return d;
}
__device__ __forceinline__ ull pack2(float lo, float hi)
{
    ull d;
    asm("mov.b64 %0, {%1, %2};" : "=l"(d) : "f"(lo), "f"(hi));
    return d;
}
__device__ __forceinline__ void unpack2(ull v, float& lo, float& hi)
{
    asm("mov.b64 {%0, %1}, %2;" : "=f"(lo), "=f"(hi) : "l"(v));
}

// ---------------------------------------------------------------------------
// Kernel 1: transform source, prescale target, init colmin (measured-best).
// ---------------------------------------------------------------------------
__global__ void __launch_bounds__(256) prep_kernel(const float* __restrict__ src,
                            const float* __restrict__ tgt,
                            const float* __restrict__ rot,
                            const float* __restrict__ trn,
                            const float* __restrict__ scl)
{
    __shared__ float M[13];
    const int pair  = blockIdx.x >> 3;
    const int pbase = (blockIdx.x & 7) * 256;

    if (threadIdx.x == 0) {
        float ax = rot[pair * 3 + 0], ay = rot[pair * 3 + 1], az = rot[pair * 3 + 2];
        float sx, cx, sy, cy, sz, cz;
        sincosf(ax, &sx, &cx);
        sincosf(ay, &sy, &cy);
        sincosf(az, &sz, &cz);
        M[0] = cy * cz;                M[1] = -cy * sz;               M[2] = sy;
        M[3] = cx * sz + sx * sy * cz; M[4] = cx * cz - sx * sy * sz; M[5] = -sx * cy;
        M[6] = sx * sz - cx * sy * cz; M[7] = sx * cz + cx * sy * sz; M[8] = cx * cy;
        M[9]  = trn[pair * 3 + 0];
        M[10] = trn[pair * 3 + 1];
        M[11] = trn[pair * 3 + 2];
        M[12] = scl[pair];
    }
    __syncthreads();

    const int idx = pair * NPTS + pbase + threadIdx.x;
    const float px = src[idx * 3 + 0];
    const float py = src[idx * 3 + 1];
    const float pz = src[idx * 3 + 2];
    const float s = M[12];
    const float qx = s * fmaf(M[0], px, fmaf(M[1], py, fmaf(M[2], pz, M[9])));
    const float qy = s * fmaf(M[3], px, fmaf(M[4], py, fmaf(M[5], pz, M[10])));
    const float qz = s * fmaf(M[6], px, fmaf(M[7], py, fmaf(M[8], pz, M[11])));

    g_y[idx] = make_float4(qx, qy, qz, qx * qx + qy * qy + qz * qz);
    g_colmin[idx] = 0x7F800000u;   // +inf bits

    if (pair < IVALS) {
        const float bx = tgt[idx * 3 + 0];
        const float by = tgt[idx * 3 + 1];
        const float bz = tgt[idx * 3 + 2];
        g_x[idx] = make_float4(-2.0f * bx, -2.0f * by, -2.0f * bz,
                               bx * bx + by * by + bz * bz);
    }
}

// ---------------------------------------------------------------------------
// Kernel 2: bidirectional chamfer, R9 pipelined structure + f32x2-packed
// inner loop (columns packed in pairs; rows dup-packed, only 4/thread to
// keep regs ~72 -> 3 CTAs/SM).
// Block (nsplit, pair): 128 target rows x 2048 source cols, 16 chunks of 128.
// Thread (tr = t>>3: 4 rows; tc = t&7: 8 column PAIRS = 16 cols).
// Per 2 evals: 3 fma2 + 1 add2 (fma pipe) + 4 FMNMX (alu) = 8 issues (was 12).
//   d2pair = add2(fma2(xx, yx, fma2(xy, yy, fma2(xz, yz, yw))), x2dup)
// y operands packed for free: SoA shared, LDS.64 at even column index.
// ---------------------------------------------------------------------------
__global__ void __launch_bounds__(256, 3) chamfer_kernel()
{
    const int pair   = blockIdx.y;
    const int nsplit = blockIdx.x;
    const int t  = threadIdx.x;
    const int tr = t >> 3;        // 0..31 : 4-row group
    const int tc = t & 7;         // 0..7  : 8 column pairs

    __shared__ __align__(16) float s_yx[2][128];
    __shared__ __align__(16) float s_yy[2][128];
    __shared__ __align__(16) float s_yz[2][128];
    __shared__ __align__(16) float s_yw[2][128];
    __shared__ float s_red[2][32][130];
    __shared__ float s_sum[8];

    const float4* gx = g_x + (pair & 15) * NPTS + nsplit * 128;
    const float4* gy = g_y + pair * NPTS;
    unsigned* cmin = g_colmin + pair * NPTS;

    // dup-packed x operands: 4 rows -> 32 registers
    ull xxp[4], xyp[4], xzp[4], xwp[4];
#pragma unroll
    for (int i = 0; i < 4; i++) {
        float4 xf = gx[tr * 4 + i];
        xxp[i] = pack2(xf.x, xf.x);
        xyp[i] = pack2(xf.y, xf.y);
        xzp[i] = pack2(xf.z, xf.z);
        xwp[i] = pack2(xf.w, xf.w);
    }

    float rm[4];
#pragma unroll
    for (int i = 0; i < 4; i++) rm[i] = 3.4e38f;

    // prologue: stage chunk 0 (SoA transpose at staging)
    if (t < 128) {
        float4 y = gy[t];
        s_yx[0][t] = y.x; s_yy[0][t] = y.y; s_yz[0][t] = y.z; s_yw[0][t] = y.w;
    }
    __syncthreads();

    for (int c = 0; c < 16; c++) {
        // issue next chunk's load early (hidden behind compute)
        float4 nxt;
        if (c < 15 && t < 128) nxt = gy[(c + 1) * 128 + t];

        const int b = c & 1;

        float cmlo[8], cmhi[8];
#pragma unroll
        for (int p = 0; p < 8; p++) { cmlo[p] = 3.4e38f; cmhi[p] = 3.4e38f; }

#pragma unroll
        for (int p = 0; p < 8; p++) {
            const int cp = 2 * (tc + 8 * p);           // even column index
            const ull yx = *(const ull*)(&s_yx[b][cp]); // (y_j, y_{j+1})
            const ull yy = *(const ull*)(&s_yy[b][cp]);
            const ull yz = *(const ull*)(&s_yz[b][cp]);
            const ull yw = *(const ull*)(&s_yw[b][cp]);
#pragma unroll
            for (int i = 0; i < 4; i++) {
                ull c2 = fma2(xzp[i], yz, yw);
                c2 = fma2(xyp[i], yy, c2);
                c2 = fma2(xxp[i], yx, c2);
                ull d2 = add2(c2, xwp[i]);
                float dlo, dhi;
                unpack2(d2, dlo, dhi);
                rm[i]   = fminf(rm[i], fminf(dlo, dhi));
                cmlo[p] = fminf(cmlo[p], dlo);
                cmhi[p] = fminf(cmhi[p], dhi);
            }
        }

        // stage col-min partials + next y buffer, then the chunk's ONE barrier
#pragma unroll
        for (int p = 0; p < 8; p++) {
            s_red[b][tr][2 * (tc + 8 * p)]     = cmlo[p];
            s_red[b][tr][2 * (tc + 8 * p) + 1] = cmhi[p];
        }
        if (c < 15 && t < 128) {
            s_yx[b ^ 1][t] = nxt.x; s_yy[b ^ 1][t] = nxt.y;
            s_yz[b ^ 1][t] = nxt.z; s_yw[b ^ 1][t] = nxt.w;
        }
        __syncthreads();

        // reduce + atomic AFTER the barrier: overlaps next chunk's compute
        if (t < 128) {
            float v = s_red[b][0][t];
#pragma unroll
            for (int k = 1; k < 32; k++) v = fminf(v, s_red[b][k][t]);
            v = fmaxf(v, 0.0f);          // d2 >= 0: keep uint ordering monotone
            atomicMin(&cmin[c * 128 + t], __float_as_uint(v));
        }
    }

    // row-min finalize: reduce over tc (lanes 1,2,4 apart), stage, sum
#pragma unroll
    for (int i = 0; i < 4; i++) {
        rm[i] = fminf(rm[i], __shfl_xor_sync(0xffffffffu, rm[i], 1));
        rm[i] = fminf(rm[i], __shfl_xor_sync(0xffffffffu, rm[i], 2));
        rm[i] = fminf(rm[i], __shfl_xor_sync(0xffffffffu, rm[i], 4));
    }
    float* sred = &s_red[0][0][0];
    if (tc == 0) {
#pragma unroll
        for (int i = 0; i < 4; i++) sred[tr * 4 + i] = rm[i];
    }
    __syncthreads();

    float total = (t < 128) ? sred[t] : 0.0f;
#pragma unroll
    for (int off = 16; off > 0; off >>= 1)
        total += __shfl_down_sync(0xffffffffu, total, off);
    if ((t & 31) == 0) s_sum[t >> 5] = total;
    __syncthreads();
    if (t == 0) {
        g_rowpart[pair * 16 + nsplit] =
            s_sum[0] + s_sum[1] + s_sum[2] + s_sum[3] +
            s_sum[4] + s_sum[5] + s_sum[6] + s_sum[7];
    }
}

// ---------------------------------------------------------------------------
// Kernel 3: per-pair means and combine
// ---------------------------------------------------------------------------
__global__ void final_kernel(float* __restrict__ out)
{
    const int pair = blockIdx.x;
    const int t = threadIdx.x;
    float local = 0.0f;
#pragma unroll
    for (int k = 0; k < 8; k++)
        local += __uint_as_float(g_colmin[pair * NPTS + t + 256 * k]);
    if (t < 16) local += g_rowpart[pair * 16 + t];

    __shared__ float sbuf[256];
    sbuf[t] = local;
    __syncthreads();
#pragma unroll
    for (int s = 128; s > 0; s >>= 1) {
        if (t < s) sbuf[t] += sbuf[t + s];
        __syncthreads();
    }
    if (t == 0) out[pair] = sbuf[0] * (1.0f / 2048.0f);
}

// ---------------------------------------------------------------------------
extern "C" void kernel_launch(void* const* d_in, const int* in_sizes, int n_in,
                              void* d_out, int out_size)
{
    const float* src = (const float*)d_in[0];   // [4,16,2048,3]
    const float* tgt = (const float*)d_in[1];   // [16,2048,3]
    const float* rot = (const float*)d_in[2];   // [4,16,3]
    const float* trn = (const float*)d_in[3];   // [4,16,3]
    const float* scl = (const float*)d_in[4];   // [4,16]
    (void)in_sizes; (void)n_in; (void)out_size;

    prep_kernel<<<512, 256>>>(src, tgt, rot, trn, scl);
    chamfer_kernel<<<dim3(16, PAIRS), 256>>>();
    final_kernel<<<PAIRS, 256>>>((float*)d_out);
}

// round 14
// speedup vs baseline: 1.0541x; 1.0306x over previous
#include <cuda_runtime.h>
#include <math.h>

#define NPTS  2048
#define PAIRS 64
#define IVALS 16

// ---- scratch (no allocations allowed) --------------------------------------
__device__ float4   g_y[PAIRS * NPTS];      // transformed source: xyz + |y|^2
__device__ float4   g_x[IVALS * NPTS];      // target prescaled: -2x,-2y,-2z, |x|^2
__device__ unsigned g_colmin[PAIRS * NPTS]; // per-(pair,m) min d2, uint bits
__device__ float    g_rowpart[PAIRS * 16];  // per-(pair,nsplit) row-min sums

// FFMA-imm (rt 1 on sm_103a) add: d = a*1.0 + c, kept out of nvcc's folder.
__device__ __forceinline__ float add_via_ffma_imm(float a, float c)
{
    float d;
    asm("fma.rn.f32 %0, %1, 0f3F800000, %2;" : "=f"(d) : "f"(a), "f"(c));
    return d;
}

// ---------------------------------------------------------------------------
// Kernel 1: transform source, prescale target, init colmin (measured-best).
// ---------------------------------------------------------------------------
__global__ void __launch_bounds__(256) prep_kernel(const float* __restrict__ src,
                            const float* __restrict__ tgt,
                            const float* __restrict__ rot,
                            const float* __restrict__ trn,
                            const float* __restrict__ scl)
{
    __shared__ float M[13];
    const int pair  = blockIdx.x >> 3;
    const int pbase = (blockIdx.x & 7) * 256;

    if (threadIdx.x == 0) {
        float ax = rot[pair * 3 + 0], ay = rot[pair * 3 + 1], az = rot[pair * 3 + 2];
        float sx, cx, sy, cy, sz, cz;
        sincosf(ax, &sx, &cx);
        sincosf(ay, &sy, &cy);
        sincosf(az, &sz, &cz);
        M[0] = cy * cz;                M[1] = -cy * sz;               M[2] = sy;
        M[3] = cx * sz + sx * sy * cz; M[4] = cx * cz - sx * sy * sz; M[5] = -sx * cy;
        M[6] = sx * sz - cx * sy * cz; M[7] = sx * cz + cx * sy * sz; M[8] = cx * cy;
        M[9]  = trn[pair * 3 + 0];
        M[10] = trn[pair * 3 + 1];
        M[11] = trn[pair * 3 + 2];
        M[12] = scl[pair];
    }
    __syncthreads();

    const int idx = pair * NPTS + pbase + threadIdx.x;
    const float px = src[idx * 3 + 0];
    const float py = src[idx * 3 + 1];
    const float pz = src[idx * 3 + 2];
    const float s = M[12];
    const float qx = s * fmaf(M[0], px, fmaf(M[1], py, fmaf(M[2], pz, M[9])));
    const float qy = s * fmaf(M[3], px, fmaf(M[4], py, fmaf(M[5], pz, M[10])));
    const float qz = s * fmaf(M[6], px, fmaf(M[7], py, fmaf(M[8], pz, M[11])));

    g_y[idx] = make_float4(qx, qy, qz, qx * qx + qy * qy + qz * qz);
    g_colmin[idx] = 0x7F800000u;   // +inf bits

    if (pair < IVALS) {
        const float bx = tgt[idx * 3 + 0];
        const float by = tgt[idx * 3 + 1];
        const float bz = tgt[idx * 3 + 2];
        g_x[idx] = make_float4(-2.0f * bx, -2.0f * by, -2.0f * bz,
                               bx * bx + by * by + bz * bz);
    }
}

// ---------------------------------------------------------------------------
// Kernel 2: bidirectional chamfer (R9 pipelined loop) with the colmin add
// emitted as FFMA-imm (rt 1) instead of FADD (rt 2): fma-pipe budget per
// warp-eval drops 8 -> 7 cycles (the binding pipe).
// Block (nsplit, pair): 128 target rows x 2048 source cols, 16 chunks of 128.
// One barrier per chunk; double-buffered s_y and s_red; col-min reduce +
// atomicMin after the barrier overlaps the next chunk's compute.
//   c  = fma(xx,yx, fma(xy,yy, fma(xz,yz, yw)))   // |y|^2 - 2 x.y
//   rowmin over c (x2 deferred), colmin over ffma_imm(x2, 1.0, c).
// ---------------------------------------------------------------------------
__global__ void __launch_bounds__(256, 3) chamfer_kernel()
{
    const int pair   = blockIdx.y;
    const int nsplit = blockIdx.x;
    const int t  = threadIdx.x;
    const int tn = t >> 4;
    const int tm = t & 15;

    __shared__ float4 s_y[2][128];
    __shared__ float  s_red[2][16][129];
    __shared__ float  s_sum[8];

    const float4* gx = g_x + (pair & 15) * NPTS + nsplit * 128;
    const float4* gy = g_y + pair * NPTS;
    unsigned* cmin = g_colmin + pair * NPTS;

    float4 xf[8];
#pragma unroll
    for (int i = 0; i < 8; i++) xf[i] = gx[tn * 8 + i];

    float rm[8];
#pragma unroll
    for (int i = 0; i < 8; i++) rm[i] = 3.4e38f;

    // prologue: stage chunk 0
    if (t < 128) s_y[0][t] = gy[t];
    __syncthreads();

    for (int c = 0; c < 16; c++) {
        // issue next chunk's load early (hidden behind compute)
        float4 nxt;
        if (c < 15 && t < 128) nxt = gy[(c + 1) * 128 + t];

        const float4* yb = &s_y[c & 1][0];

        float cm[8];
#pragma unroll
        for (int j = 0; j < 8; j++) cm[j] = 3.4e38f;

#pragma unroll
        for (int jj = 0; jj < 8; jj++) {
            const float4 y = yb[tm + 16 * jj];
#pragma unroll
            for (int i = 0; i < 8; i++) {
                float cc = fmaf(xf[i].x, y.x,
                           fmaf(xf[i].y, y.y,
                           fmaf(xf[i].z, y.z, y.w)));
                rm[i]  = fminf(rm[i], cc);
                cm[jj] = fminf(cm[jj], add_via_ffma_imm(xf[i].w, cc));
            }
        }

        // stage col-min partials + next y buffer, then the chunk's ONE barrier
#pragma unroll
        for (int jj = 0; jj < 8; jj++) s_red[c & 1][tn][tm + 16 * jj] = cm[jj];
        if (c < 15 && t < 128) s_y[(c + 1) & 1][t] = nxt;
        __syncthreads();

        // reduce + atomic AFTER the barrier: overlaps next chunk's compute
        if (t < 128) {
            float v = s_red[c & 1][0][t];
#pragma unroll
            for (int k = 1; k < 16; k++) v = fminf(v, s_red[c & 1][k][t]);
            v = fmaxf(v, 0.0f);          // d2 >= 0: keep uint ordering monotone
            atomicMin(&cmin[c * 128 + t], __float_as_uint(v));
        }
    }

    // finalize row mins: add deferred x2, reduce over tm, sum the 128 rows
#pragma unroll
    for (int i = 0; i < 8; i++) s_red[0][tm][tn * 8 + i] = rm[i] + xf[i].w;
    __syncthreads();

    float total = 0.0f;
    if (t < 128) {
        float v = s_red[0][0][t];
#pragma unroll
        for (int k = 1; k < 16; k++) v = fminf(v, s_red[0][k][t]);
        total = v;
    }
#pragma unroll
    for (int off = 16; off > 0; off >>= 1)
        total += __shfl_down_sync(0xffffffffu, total, off);
    if ((t & 31) == 0) s_sum[t >> 5] = total;
    __syncthreads();
    if (t == 0) {
        g_rowpart[pair * 16 + nsplit] =
            s_sum[0] + s_sum[1] + s_sum[2] + s_sum[3] +
            s_sum[4] + s_sum[5] + s_sum[6] + s_sum[7];
    }
}

// ---------------------------------------------------------------------------
// Kernel 3: per-pair means and combine
// ---------------------------------------------------------------------------
__global__ void final_kernel(float* __restrict__ out)
{
    const int pair = blockIdx.x;
    const int t = threadIdx.x;
    float local = 0.0f;
#pragma unroll
    for (int k = 0; k < 8; k++)
        local += __uint_as_float(g_colmin[pair * NPTS + t + 256 * k]);
    if (t < 16) local += g_rowpart[pair * 16 + t];

    __shared__ float sbuf[256];
    sbuf[t] = local;
    __syncthreads();
#pragma unroll
    for (int s = 128; s > 0; s >>= 1) {
        if (t < s) sbuf[t] += sbuf[t + s];
        __syncthreads();
    }
    if (t == 0) out[pair] = sbuf[0] * (1.0f / 2048.0f);
}

// ---------------------------------------------------------------------------
extern "C" void kernel_launch(void* const* d_in, const int* in_sizes, int n_in,
                              void* d_out, int out_size)
{
    const float* src = (const float*)d_in[0];   // [4,16,2048,3]
    const float* tgt = (const float*)d_in[1];   // [16,2048,3]
    const float* rot = (const float*)d_in[2];   // [4,16,3]
    const float* trn = (const float*)d_in[3];   // [4,16,3]
    const float* scl = (const float*)d_in[4];   // [4,16]
    (void)in_sizes; (void)n_in; (void)out_size;

    prep_kernel<<<512, 256>>>(src, tgt, rot, trn, scl);
    chamfer_kernel<<<dim3(16, PAIRS), 256>>>();
    final_kernel<<<PAIRS, 256>>>((float*)d_out);
}

// round 15
// speedup vs baseline: 1.0595x; 1.0052x over previous
#include <cuda_runtime.h>
#include <math.h>

#define NPTS  2048
#define PAIRS 64
#define IVALS 16

// ---- scratch (no allocations allowed) --------------------------------------
// g_colmin holds ~bits(min d2) accumulated with atomicMax (identity 0 == BSS
// init). final_kernel decodes and resets to 0, re-arming for graph replays.
__device__ unsigned g_colmin[PAIRS * NPTS];
__device__ float    g_rowpart[PAIRS * 16];

// FFMA-imm add: d = a*1.0 + c (kept out of nvcc's FADD folder).
__device__ __forceinline__ float add_via_ffma_imm(float a, float c)
{
    float d;
    asm("fma.rn.f32 %0, %1, 0f3F800000, %2;" : "=f"(d) : "f"(a), "f"(c));
    return d;
}

// ---------------------------------------------------------------------------
// Kernel 1 (the ONLY heavy kernel): bidirectional chamfer with fused in-block
// source transform — no prep kernel, no init kernel.
// Block (nsplit, pair): owns source rows y[nsplit*128 .. +128) (transformed
// in-block: thread 0 builds the scale-folded matrix, 128 threads transform
// one point each into shared), streams ALL 2048 target points in 16 chunks
// of 128 (raw tgt, |x|^2 computed at staging).
// Register rows: yf[i] = (-2qx, -2qy, -2qz, |q|^2). Shared cols: (x,y,z,|x|^2).
//   c  = fma(yfx,xx, fma(yfy,xy, fma(yfz,xz, q2)))  // |y|^2 - 2 x.y
//   d2 = ffma_imm(x2, 1.0, c)                       // full distance
// rowmin (source side) completes in block -> g_rowpart.
// colmin (target side) -> shared reduce -> atomicMax of ~bits(d2).
// R9's pipelined structure: one barrier per chunk, double-buffered s_x/s_red,
// flush after the barrier overlaps the next chunk's compute.
// ---------------------------------------------------------------------------
__global__ void __launch_bounds__(256, 3) chamfer_kernel(
    const float* __restrict__ src,
    const float* __restrict__ tgt,
    const float* __restrict__ rot,
    const float* __restrict__ trn,
    const float* __restrict__ scl)
{
    const int pair   = blockIdx.y;
    const int nsplit = blockIdx.x;
    const int t  = threadIdx.x;
    const int tn = t >> 4;
    const int tm = t & 15;

    __shared__ float  s_m[12];
    __shared__ float4 s_yrow[128];        // this block's transformed rows
    __shared__ float4 s_x[2][128];        // streamed target chunks
    __shared__ float  s_red[2][16][129];
    __shared__ float  s_sum[8];

    const float* tg = tgt + (size_t)(pair & 15) * NPTS * 3;

    // -- thread 0: scale-folded rotation matrix --------------------------------
    if (t == 0) {
        float ax = rot[pair * 3 + 0], ay = rot[pair * 3 + 1], az = rot[pair * 3 + 2];
        float sx, cx, sy, cy, sz, cz;
        sincosf(ax, &sx, &cx);
        sincosf(ay, &sy, &cy);
        sincosf(az, &sz, &cz);
        const float s = scl[pair];
        s_m[0] = s * (cy * cz);                s_m[1] = s * (-cy * sz);               s_m[2] = s * sy;
        s_m[3] = s * (cx * sz + sx * sy * cz); s_m[4] = s * (cx * cz - sx * sy * sz); s_m[5] = s * (-sx * cy);
        s_m[6] = s * (sx * sz - cx * sy * cz); s_m[7] = s * (sx * cz + cx * sy * sz); s_m[8] = s * (cx * cy);
        s_m[9]  = s * trn[pair * 3 + 0];
        s_m[10] = s * trn[pair * 3 + 1];
        s_m[11] = s * trn[pair * 3 + 2];
    }
    // -- threads 128..255: stage target chunk 0 (independent of the matrix) ----
    if (t >= 128) {
        const int j = t - 128;
        const float xx = tg[j * 3 + 0];
        const float xy = tg[j * 3 + 1];
        const float xz = tg[j * 3 + 2];
        s_x[0][j] = make_float4(xx, xy, xz,
                                fmaf(xx, xx, fmaf(xy, xy, xz * xz)));
    }
    __syncthreads();

    // -- threads 0..127: transform one source point each ------------------------
    if (t < 128) {
        const float* sp = src + ((size_t)pair * NPTS + nsplit * 128 + t) * 3;
        const float px = sp[0], py = sp[1], pz = sp[2];
        const float qx = fmaf(s_m[0], px, fmaf(s_m[1], py, fmaf(s_m[2], pz, s_m[9])));
        const float qy = fmaf(s_m[3], px, fmaf(s_m[4], py, fmaf(s_m[5], pz, s_m[10])));
        const float qz = fmaf(s_m[6], px, fmaf(s_m[7], py, fmaf(s_m[8], pz, s_m[11])));
        const float q2 = fmaf(qx, qx, fmaf(qy, qy, qz * qz));
        s_yrow[t] = make_float4(-2.0f * qx, -2.0f * qy, -2.0f * qz, q2);
    }
    __syncthreads();

    float4 yf[8];
#pragma unroll
    for (int i = 0; i < 8; i++) yf[i] = s_yrow[tn * 8 + i];

    unsigned* cmin = g_colmin + pair * NPTS;

    float rm[8];
#pragma unroll
    for (int i = 0; i < 8; i++) rm[i] = 3.4e38f;

    for (int c = 0; c < 16; c++) {
        // issue next chunk's raw loads early (hidden behind compute)
        float nx, ny, nz;
        if (c < 15 && t < 128) {
            const float* tp = tg + ((c + 1) * 128 + t) * 3;
            nx = tp[0]; ny = tp[1]; nz = tp[2];
        }

        const float4* xb = &s_x[c & 1][0];

        float cm[8];
#pragma unroll
        for (int j = 0; j < 8; j++) cm[j] = 3.4e38f;

#pragma unroll
        for (int jj = 0; jj < 8; jj++) {
            const float4 x = xb[tm + 16 * jj];
#pragma unroll
            for (int i = 0; i < 8; i++) {
                float cc = fmaf(yf[i].x, x.x,
                           fmaf(yf[i].y, x.y,
                           fmaf(yf[i].z, x.z, yf[i].w)));
                float d2 = add_via_ffma_imm(x.w, cc);
                rm[i]  = fminf(rm[i], d2);
                cm[jj] = fminf(cm[jj], d2);
            }
        }

        // stage col-min partials + next x buffer, then the chunk's ONE barrier
#pragma unroll
        for (int jj = 0; jj < 8; jj++) s_red[c & 1][tn][tm + 16 * jj] = cm[jj];
        if (c < 15 && t < 128)
            s_x[(c + 1) & 1][t] = make_float4(nx, ny, nz,
                                              fmaf(nx, nx, fmaf(ny, ny, nz * nz)));
        __syncthreads();

        // reduce + atomic AFTER the barrier: overlaps next chunk's compute
        if (t < 128) {
            float v = s_red[c & 1][0][t];
#pragma unroll
            for (int k = 1; k < 16; k++) v = fminf(v, s_red[c & 1][k][t]);
            v = fmaxf(v, 0.0f);            // d2 >= 0 keeps bit ordering monotone
            atomicMax(&cmin[c * 128 + t], ~__float_as_uint(v));
        }
    }

    // finalize row mins (source side): reduce over tm, sum the 128 rows
#pragma unroll
    for (int i = 0; i < 8; i++) s_red[0][tm][tn * 8 + i] = rm[i];
    __syncthreads();

    float total = 0.0f;
    if (t < 128) {
        float v = s_red[0][0][t];
#pragma unroll
        for (int k = 1; k < 16; k++) v = fminf(v, s_red[0][k][t]);
        total = v;
    }
#pragma unroll
    for (int off = 16; off > 0; off >>= 1)
        total += __shfl_down_sync(0xffffffffu, total, off);
    if ((t & 31) == 0) s_sum[t >> 5] = total;
    __syncthreads();
    if (t == 0) {
        g_rowpart[pair * 16 + nsplit] =
            s_sum[0] + s_sum[1] + s_sum[2] + s_sum[3] +
            s_sum[4] + s_sum[5] + s_sum[6] + s_sum[7];
    }
}

// ---------------------------------------------------------------------------
// Kernel 2: per-pair means + combine; decodes ~bits colmin and RESETS it to 0
// (the atomicMax identity) so the next graph replay starts clean.
// ---------------------------------------------------------------------------
__global__ void final_kernel(float* __restrict__ out)
{
    const int pair = blockIdx.x;
    const int t = threadIdx.x;
    float local = 0.0f;
#pragma unroll
    for (int k = 0; k < 8; k++) {
        unsigned* p = &g_colmin[pair * NPTS + t + 256 * k];
        local += __uint_as_float(~(*p));
        *p = 0u;                            // re-arm for next replay
    }
    if (t < 16) local += g_rowpart[pair * 16 + t];

    __shared__ float sbuf[256];
    sbuf[t] = local;
    __syncthreads();
#pragma unroll
    for (int s = 128; s > 0; s >>= 1) {
        if (t < s) sbuf[t] += sbuf[t + s];
        __syncthreads();
    }
    if (t == 0) out[pair] = sbuf[0] * (1.0f / 2048.0f);
}

// ---------------------------------------------------------------------------
extern "C" void kernel_launch(void* const* d_in, const int* in_sizes, int n_in,
                              void* d_out, int out_size)
{
    const float* src = (const float*)d_in[0];   // [4,16,2048,3]
    const float* tgt = (const float*)d_in[1];   // [16,2048,3]
    const float* rot = (const float*)d_in[2];   // [4,16,3]
    const float* trn = (const float*)d_in[3];   // [4,16,3]
    const float* scl = (const float*)d_in[4];   // [4,16]
    (void)in_sizes; (void)n_in; (void)out_size;

    chamfer_kernel<<<dim3(16, PAIRS), 256>>>(src, tgt, rot, trn, scl);
    final_kernel<<<PAIRS, 256>>>((float*)d_out);
}